// round 4
// baseline (speedup 1.0000x reference)
#include <cuda_runtime.h>

#define QB      16
#define THREADS 256
#define S_Q     16384.0f            // quantization scale (2^14)
#define K_EPI   (5.0f / 16384.0f)   // exact: 5 * 2^-14

// SIMD SAD: d = c + |a.h0 - b.h0| + |a.h1 - b.h1|  (u16 halves, scalar-merge)
static __device__ __forceinline__ unsigned vsad2_add(unsigned a, unsigned b, unsigned c) {
    unsigned d;
    asm("vabsdiff2.u32.u32.u32.add %0, %1, %2, %3;" : "=r"(d) : "r"(a), "r"(b), "r"(c));
    return d;
}

static __device__ __forceinline__ unsigned pack_q(float x, float y) {
    const int a = __float2int_rn(x * S_Q);
    const int b = __float2int_rn(y * S_Q);
    return (unsigned)(a & 0xFFFF) | ((unsigned)b << 16);
}

// C[bq, t] = 5 * sum_d |qb[d] - tb[d]|  -  p_{label[t]}(bq)
// p0 = 1/(1+exp(l1-l0));  cc = fma(lab, 2*p0-1, -p0)
__global__ __launch_bounds__(THREADS)
void hm_cost_kernel(const float* __restrict__ logits,   // [32768, 2]
                    const float* __restrict__ qboxes,   // [32768, 6]
                    const int*   __restrict__ tlabels,  // [1024]
                    const float* __restrict__ tboxes,   // [1024, 6]
                    float*       __restrict__ out)      // [32768, 1024]
{
    // per q: uint4 = {dims01, dims23, dims45, bits(A)}  +  float Dn
    __shared__ __align__(16) uint4 sqA[QB];
    __shared__ float sqD[QB];

    const int tx = threadIdx.x;
    const int q0 = blockIdx.x * QB;

    // ---- cooperative query preload: QB*8 = 128 lanes used ----
    if (tx < QB * 8) {
        const int q = tx >> 3;
        const int f = tx & 7;
        const int gq = q0 + q;
        if (f < 3) {
            const float x = qboxes[gq * 6 + 2 * f];
            const float y = qboxes[gq * 6 + 2 * f + 1];
            ((unsigned*)&sqA[q])[f] = pack_q(x, y);
        } else if (f == 3) {
            const float l0 = logits[gq * 2 + 0];
            const float l1 = logits[gq * 2 + 1];
            const float p0 = 1.0f / (1.0f + __expf(l1 - l0));
            ((unsigned*)&sqA[q])[3] = __float_as_uint(-p0);   // A = -p0
        } else if (f == 4) {
            const float l0 = logits[gq * 2 + 0];
            const float l1 = logits[gq * 2 + 1];
            const float p0 = 1.0f / (1.0f + __expf(l1 - l0));
            sqD[q] = 2.0f * p0 - 1.0f;                        // Dn = p0 - p1
        }
    }

    // ---- per-thread targets: 4 rows quantized+packed (12 regs) + 4 label floats ----
    unsigned t01[4], t23[4], t45[4];
    float labf[4];
    {
        const float4* tb4 = (const float4*)(tboxes + (size_t)tx * 24);
        const float4 v0 = tb4[0], v1 = tb4[1], v2 = tb4[2];
        const float4 v3 = tb4[3], v4 = tb4[4], v5 = tb4[5];
        t01[0] = pack_q(v0.x, v0.y);  t23[0] = pack_q(v0.z, v0.w);  t45[0] = pack_q(v1.x, v1.y);
        t01[1] = pack_q(v1.z, v1.w);  t23[1] = pack_q(v2.x, v2.y);  t45[1] = pack_q(v2.z, v2.w);
        t01[2] = pack_q(v3.x, v3.y);  t23[2] = pack_q(v3.z, v3.w);  t45[2] = pack_q(v4.x, v4.y);
        t01[3] = pack_q(v4.z, v4.w);  t23[3] = pack_q(v5.x, v5.y);  t45[3] = pack_q(v5.z, v5.w);
        const int4 lb = *(const int4*)(tlabels + tx * 4);
        labf[0] = (float)lb.x;  labf[1] = (float)lb.y;
        labf[2] = (float)lb.z;  labf[3] = (float)lb.w;
    }
    __syncthreads();

    // ---- main loop ----
    char* obase = (char*)out + ((size_t)q0 * 1024 + 4 * tx) * sizeof(float);

#pragma unroll 8
    for (int q = 0; q < QB; ++q) {
        const uint4 qa = sqA[q];          // LDS.128 broadcast
        const float Dn = sqD[q];          // LDS.32 broadcast
        const float A  = __uint_as_float(qa.w);

        float4 res;
        float r[4];
#pragma unroll
        for (int p = 0; p < 4; ++p) {
            const unsigned sad = vsad2_add(qa.x, t01[p],
                                 vsad2_add(qa.y, t23[p],
                                 vsad2_add(qa.z, t45[p], 0u)));
            const float cc = fmaf(labf[p], Dn, A);
            r[p] = fmaf((float)sad, K_EPI, cc);
        }
        res.x = r[0]; res.y = r[1]; res.z = r[2]; res.w = r[3];
        *(float4*)(obase + q * 4096) = res;   // STG.128
    }
}

extern "C" void kernel_launch(void* const* d_in, const int* in_sizes, int n_in,
                              void* d_out, int out_size)
{
    const float* logits  = (const float*)d_in[0];  // (16, 2048, 2) f32
    const float* qboxes  = (const float*)d_in[1];  // (16, 2048, 6) f32
    const int*   tlabels = (const int*)  d_in[2];  // (1024,) int32
    const float* tboxes  = (const float*)d_in[3];  // (1024, 6) f32

    const int total_q = 16 * 2048;
    hm_cost_kernel<<<total_q / QB, THREADS>>>(logits, qboxes, tlabels, tboxes, (float*)d_out);
}

// round 5
// speedup vs baseline: 2.2976x; 2.2976x over previous
#include <cuda_runtime.h>
#include <cuda_fp16.h>

#define QB      16
#define THREADS 256

static __device__ __forceinline__ unsigned dup16(float x) {
    const unsigned h = __half_as_ushort(__float2half_rn(x));
    return h * 0x10001u;
}
static __device__ __forceinline__ unsigned pack16(float lo, float hi) {
    const unsigned a = __half_as_ushort(__float2half_rn(lo));
    const unsigned b = __half_as_ushort(__float2half_rn(hi));
    return a | (b << 16);
}
static __device__ __forceinline__ unsigned hadd2u(unsigned a, unsigned b) {
    __half2 r = __hadd2(*(const __half2*)&a, *(const __half2*)&b);
    return *(unsigned*)&r;
}
static __device__ __forceinline__ unsigned hfma2u(unsigned a, unsigned b, unsigned c) {
    __half2 r = __hfma2(*(const __half2*)&a, *(const __half2*)&b, *(const __half2*)&c);
    return *(unsigned*)&r;
}

// C[bq, t] = 5 * sum_d |qb[d] - tb[d]|  -  p_{label[t]}(bq)
__global__ __launch_bounds__(THREADS)
void hm_cost_kernel(const float* __restrict__ logits,   // [32768, 2]
                    const float* __restrict__ qboxes,   // [32768, 6]
                    const int*   __restrict__ tlabels,  // [1024]
                    const float* __restrict__ tboxes,   // [1024, 6]
                    float*       __restrict__ out)      // [32768, 1024]
{
    // per q: 8 u32 fields = {dup(q0)..dup(q5), dup(-p0), dup(-p1)}  (fp16x2)
    __shared__ __align__(16) unsigned sq[QB * 8];

    const int tx = threadIdx.x;
    const int q0 = blockIdx.x * QB;

    // ---- cooperative query preload: QB*8 = 128 fields ----
    if (tx < QB * 8) {
        const int q = tx >> 3;
        const int f = tx & 7;
        const int gq = q0 + q;
        unsigned v;
        if (f < 6) {
            v = dup16(qboxes[gq * 6 + f]);
        } else {
            const float l0 = logits[gq * 2 + 0];
            const float l1 = logits[gq * 2 + 1];
            const float p0 = 1.0f / (1.0f + __expf(l1 - l0));
            v = dup16((f == 6) ? -p0 : (p0 - 1.0f));   // -p0 | -p1
        }
        sq[q * 8 + f] = v;
    }

    // ---- per-thread targets: 4 rows, fp16x2 packed & negated (12 regs) + 2 label masks ----
    unsigned nt[2][6];
    unsigned lmask[2];
    {
        const float4* tb4 = (const float4*)(tboxes + (size_t)tx * 24);
        const float4 v0 = tb4[0], v1 = tb4[1], v2 = tb4[2];
        const float4 v3 = tb4[3], v4 = tb4[4], v5 = tb4[5];
        const float r0[6] = {v0.x, v0.y, v0.z, v0.w, v1.x, v1.y};
        const float r1[6] = {v1.z, v1.w, v2.x, v2.y, v2.z, v2.w};
        const float r2[6] = {v3.x, v3.y, v3.z, v3.w, v4.x, v4.y};
        const float r3[6] = {v4.z, v4.w, v5.x, v5.y, v5.z, v5.w};
#pragma unroll
        for (int d = 0; d < 6; ++d) {
            nt[0][d] = pack16(-r0[d], -r1[d]);
            nt[1][d] = pack16(-r2[d], -r3[d]);
        }
        const int4 lb = *(const int4*)(tlabels + tx * 4);
        lmask[0] = (lb.x ? 0x0000FFFFu : 0u) | (lb.y ? 0xFFFF0000u : 0u);
        lmask[1] = (lb.z ? 0x0000FFFFu : 0u) | (lb.w ? 0xFFFF0000u : 0u);
    }
    __syncthreads();

    const unsigned five2 = 0x45004500u;   // fp16x2 (5.0, 5.0)
    char* obase = (char*)out + ((size_t)q0 * 1024 + 4 * tx) * sizeof(float);

#pragma unroll 8
    for (int q = 0; q < QB; ++q) {
        const uint4 A = *(const uint4*)(sq + q * 8);       // LDS.128
        const uint4 B = *(const uint4*)(sq + q * 8 + 4);   // LDS.128
        const unsigned d0 = A.x, d1 = A.y, d2 = A.z, d3 = A.w, d4 = B.x, d5 = B.y;
        const unsigned mp0 = B.z, mp1 = B.w;

        unsigned r16[2];
#pragma unroll
        for (int p = 0; p < 2; ++p) {
            const unsigned a0 = hadd2u(d0, nt[p][0]) & 0x7FFF7FFFu;
            const unsigned a1 = hadd2u(d1, nt[p][1]) & 0x7FFF7FFFu;
            const unsigned a2 = hadd2u(d2, nt[p][2]) & 0x7FFF7FFFu;
            const unsigned a3 = hadd2u(d3, nt[p][3]) & 0x7FFF7FFFu;
            const unsigned a4 = hadd2u(d4, nt[p][4]) & 0x7FFF7FFFu;
            const unsigned a5 = hadd2u(d5, nt[p][5]) & 0x7FFF7FFFu;
            const unsigned s  = hadd2u(hadd2u(hadd2u(a0, a1), hadd2u(a2, a3)),
                                       hadd2u(a4, a5));
            const unsigned cc = (lmask[p] & mp1) | (~lmask[p] & mp0);  // 1 LOP3
            r16[p] = hfma2u(s, five2, cc);
        }
        const float2 fa = __half22float2(*(const __half2*)&r16[0]);
        const float2 fb = __half22float2(*(const __half2*)&r16[1]);
        asm volatile("st.global.cs.v4.f32 [%0], {%1, %2, %3, %4};"
                     :: "l"(obase + q * 4096),
                        "f"(fa.x), "f"(fa.y), "f"(fb.x), "f"(fb.y)
                     : "memory");
    }
}

extern "C" void kernel_launch(void* const* d_in, const int* in_sizes, int n_in,
                              void* d_out, int out_size)
{
    const float* logits  = (const float*)d_in[0];  // (16, 2048, 2) f32
    const float* qboxes  = (const float*)d_in[1];  // (16, 2048, 6) f32
    const int*   tlabels = (const int*)  d_in[2];  // (1024,) int32
    const float* tboxes  = (const float*)d_in[3];  // (1024, 6) f32

    const int total_q = 16 * 2048;
    hm_cost_kernel<<<total_q / QB, THREADS>>>(logits, qboxes, tlabels, tboxes, (float*)d_out);
}